// round 16
// baseline (speedup 1.0000x reference)
#include <cuda_runtime.h>
#include <cuda_bf16.h>
#include <math.h>
#include <cstdint>

#define T_STEPS 2048
#define BATCH 32
#define INF 128
#define HID 256

typedef unsigned long long ull;
typedef __nv_bfloat16 bf16;

// ---------------- scratch ------------------------------------------------------
__device__ float g_XW0[(size_t)T_STEPS * BATCH * 2048];   // layer-0 stacked fwd|bwd
__device__ float g_XW1[(size_t)T_STEPS * BATCH * 1024];   // layer-1 fwd
__device__ float g_OUT0[(size_t)T_STEPS * BATCH * 512];
__device__ float g_LAST[BATCH * 512];
__device__ float g_XWB1L[BATCH * 1024];
// bf16 hi/lo planes
__device__ bf16 g_A0H[(size_t)T_STEPS * BATCH * INF];
__device__ bf16 g_A0L[(size_t)T_STEPS * BATCH * INF];
__device__ bf16 g_O0H[(size_t)T_STEPS * BATCH * 512];
__device__ bf16 g_O0L[(size_t)T_STEPS * BATCH * 512];
__device__ bf16 g_W0SH[2048 * 128], g_W0SL[2048 * 128];   // stacked layer-0 weights
__device__ bf16 g_W1FH[1024 * 512], g_W1FL[1024 * 512];
__device__ float g_B0S[2048];                              // stacked layer-0 bias

__device__ __forceinline__ float sigf(float x) {
    return __fdividef(1.0f, 1.0f + __expf(-x));
}
__device__ __forceinline__ float tanhf_fast(float x) {
    float e = __expf(2.0f * x);
    return 1.0f - __fdividef(2.0f, e + 1.0f);
}
__device__ __forceinline__ uint32_t smem_u32(const void* p) {
    uint32_t a;
    asm("{ .reg .u64 t; cvta.to.shared.u64 t, %1; cvt.u32.u64 %0, t; }" : "=r"(a) : "l"(p));
    return a;
}
// Tight spin on LOCAL mbarrier (acquire.cluster orders remote st.async data).
__device__ __forceinline__ void mbar_wait_spin(uint32_t addr, unsigned phase) {
    asm volatile(
        "{\n\t.reg .pred P;\n\t"
        "WAIT_%=:\n\t"
        "mbarrier.test_wait.parity.acquire.cluster.shared::cta.b64 P, [%0], %1;\n\t"
        "@!P bra.uni WAIT_%=;\n\t}"
        :: "r"(addr), "r"(phase) : "memory");
}
__device__ __forceinline__ void cp16(uint32_t saddr, const void* gaddr) {
    asm volatile("cp.async.cg.shared.global [%0], [%1], 16;" :: "r"(saddr), "l"(gaddr));
}
__device__ __forceinline__ void ldsm4(uint32_t* r, uint32_t addr) {
    asm volatile("ldmatrix.sync.aligned.m8n8.x4.shared.b16 {%0,%1,%2,%3}, [%4];"
                 : "=r"(r[0]), "=r"(r[1]), "=r"(r[2]), "=r"(r[3]) : "r"(addr));
}
__device__ __forceinline__ void ldsm2t(uint32_t* r, uint32_t addr) {
    asm volatile("ldmatrix.sync.aligned.m8n8.x2.trans.shared.b16 {%0,%1}, [%2];"
                 : "=r"(r[0]), "=r"(r[1]) : "r"(addr));
}
__device__ __forceinline__ void mma_bf16(float* d, const uint32_t* a, const uint32_t* b) {
    asm volatile(
        "mma.sync.aligned.m16n8k16.row.col.f32.bf16.bf16.f32 "
        "{%0,%1,%2,%3}, {%4,%5,%6,%7}, {%8,%9}, {%0,%1,%2,%3};"
        : "+f"(d[0]), "+f"(d[1]), "+f"(d[2]), "+f"(d[3])
        : "r"(a[0]), "r"(a[1]), "r"(a[2]), "r"(a[3]), "r"(b[0]), "r"(b[1]));
}
__device__ __forceinline__ void split1(float v, bf16& h, bf16& l) {
    h = __float2bfloat16(v);
    l = __float2bfloat16(v - __bfloat162float(h));
}
__device__ __forceinline__ void pack2bf(float2 w, uint32_t& hi, uint32_t& lo) {
    bf16 h0, l0, h1, l1;
    split1(w.x, h0, l0); split1(w.y, h1, l1);
    __nv_bfloat162 hv; hv.x = h0; hv.y = h1;
    __nv_bfloat162 lv; lv.x = l0; lv.y = l1;
    hi = *(uint32_t*)&hv; lo = *(uint32_t*)&lv;
}

// ---------------- transpose x[B,1,IN,T] -> A0 hi/lo [(t*B+b), f] -----------------
__global__ void transpose_x(const float* __restrict__ x,
                            bf16* __restrict__ A0h, bf16* __restrict__ A0l) {
    __shared__ float tile[32][33];
    int b = blockIdx.z;
    int f0 = blockIdx.y * 32, t0 = blockIdx.x * 32;
    int tx = threadIdx.x, ty = threadIdx.y;
#pragma unroll
    for (int i = 0; i < 32; i += 8)
        tile[ty + i][tx] = x[((size_t)b * INF + (f0 + ty + i)) * T_STEPS + t0 + tx];
    __syncthreads();
#pragma unroll
    for (int i = 0; i < 32; i += 8) {
        float v = tile[tx][ty + i];
        size_t idx = (((size_t)(t0 + ty + i)) * BATCH + b) * INF + f0 + tx;
        bf16 h, l; split1(v, h, l);
        A0h[idx] = h; A0l[idx] = l;
    }
}

// ---------------- split layer-0 weights into STACKED planes + bias concat --------
__global__ void split_w0(const float* __restrict__ wf, const float* __restrict__ wb,
                         bf16* __restrict__ hiS, bf16* __restrict__ loS,
                         const float* __restrict__ bf_, const float* __restrict__ bb_,
                         float* __restrict__ biasS, int n) {
    int i = blockIdx.x * blockDim.x + threadIdx.x;
    if (i < n) {
        bf16 h, l;
        split1(wf[i], h, l); hiS[i] = h;     loS[i] = l;
        split1(wb[i], h, l); hiS[n + i] = h; loS[n + i] = l;
        if (i < 1024) { biasS[i] = bf_[i]; biasS[1024 + i] = bb_[i]; }
    }
}
__global__ void split_bf16(const float* __restrict__ in, bf16* __restrict__ hi,
                           bf16* __restrict__ lo, int n) {
    int i = blockIdx.x * blockDim.x + threadIdx.x;
    if (i < n) { bf16 h, l; split1(in[i], h, l); hi[i] = h; lo[i] = l; }
}

// ---------------- HMMA split-bf16 GEMM: C = A(f32~hi+lo) * W^T + bias ----------
__global__ void __launch_bounds__(256) gemm_mma(
    const bf16* __restrict__ Ah, const bf16* __restrict__ Al,
    const bf16* __restrict__ Wh, const bf16* __restrict__ Wl,
    const float* __restrict__ bias, float* __restrict__ C,
    int K, int N_total)
{
    extern __shared__ char sraw[];
    const uint32_t base = (smem_u32(sraw) + 127u) & ~127u;
    const uint32_t As = base;
    const uint32_t Bs = base + 40960u;

    const int tid = threadIdx.x;
    const int lane = tid & 31, wid = tid >> 5;
    const int wm = wid & 1, wn = wid >> 1;
    const int bm = blockIdx.y * 128, bn = blockIdx.x * 128;

    const int a_ro = ((lane >> 3) & 1) * 8 + (lane & 7);
    const int a_co = (lane >> 4) * 16;
    const int b_ro = ((lane >> 4) << 3) + (lane & 7);
    const int b_co = ((lane >> 3) & 1) * 16;

    const int c0 = tid * 2;

    float acc[4][4][4];
#pragma unroll
    for (int mt = 0; mt < 4; ++mt)
#pragma unroll
        for (int nt = 0; nt < 4; ++nt)
#pragma unroll
            for (int e = 0; e < 4; ++e) acc[mt][nt][e] = 0.f;

    const int nst = K >> 5;
    int buf = 0;

#pragma unroll
    for (int h = 0; h < 2; ++h) {
        int c = c0 + h, row = c >> 2, blk = c & 3;
        size_t ga = (size_t)(bm + row) * K + blk * 8;
        size_t gw = (size_t)(bn + row) * K + blk * 8;
        uint32_t so = (uint32_t)(row * 80 + blk * 16);
        cp16(As + so,          Ah + ga);
        cp16(As + 10240u + so, Al + ga);
        cp16(Bs + so,          Wh + gw);
        cp16(Bs + 10240u + so, Wl + gw);
    }
    asm volatile("cp.async.commit_group;");

    for (int st = 0; st < nst; ++st) {
        if (st + 1 < nst) {
            const int nb = buf ^ 1;
            const int k0 = (st + 1) * 32;
#pragma unroll
            for (int h = 0; h < 2; ++h) {
                int c = c0 + h, row = c >> 2, blk = c & 3;
                size_t ga = (size_t)(bm + row) * K + k0 + blk * 8;
                size_t gw = (size_t)(bn + row) * K + k0 + blk * 8;
                uint32_t so = (uint32_t)(nb * 20480 + row * 80 + blk * 16);
                cp16(As + so,          Ah + ga);
                cp16(As + 10240u + so, Al + ga);
                cp16(Bs + so,          Wh + gw);
                cp16(Bs + 10240u + so, Wl + gw);
            }
            asm volatile("cp.async.commit_group;");
            asm volatile("cp.async.wait_group 1;");
        } else {
            asm volatile("cp.async.wait_group 0;");
        }
        __syncthreads();

        const uint32_t Ab = As + buf * 20480u;
        const uint32_t Bb = Bs + buf * 20480u;
#pragma unroll
        for (int ks = 0; ks < 2; ++ks) {
            const uint32_t kb = ks * 32u;
            uint32_t bh[2][4], bl[2][4];
#pragma unroll
            for (int pr = 0; pr < 2; ++pr) {
                uint32_t ro = (uint32_t)((wn * 32 + pr * 16 + b_ro) * 80) + kb + b_co;
                ldsm4(bh[pr], Bb + ro);
                ldsm4(bl[pr], Bb + 10240u + ro);
            }
#pragma unroll
            for (int mt = 0; mt < 4; ++mt) {
                uint32_t ah[4], al[4];
                uint32_t ro = (uint32_t)((wm * 64 + mt * 16 + a_ro) * 80) + kb + a_co;
                ldsm4(ah, Ab + ro);
                ldsm4(al, Ab + 10240u + ro);
#pragma unroll
                for (int nt = 0; nt < 4; ++nt) {
                    const uint32_t* bfh = &bh[nt >> 1][(nt & 1) * 2];
                    const uint32_t* bfl = &bl[nt >> 1][(nt & 1) * 2];
                    mma_bf16(acc[mt][nt], ah, bfh);
                    mma_bf16(acc[mt][nt], al, bfh);
                    mma_bf16(acc[mt][nt], ah, bfl);
                }
            }
        }
        __syncthreads();
        buf ^= 1;
    }

    const int g = lane >> 2, tg = lane & 3;
#pragma unroll
    for (int nt = 0; nt < 4; ++nt) {
        const int col = bn + wn * 32 + nt * 8 + tg * 2;
        const float b0 = bias[col], b1 = bias[col + 1];
#pragma unroll
        for (int mt = 0; mt < 4; ++mt) {
            const int row = bm + wm * 64 + mt * 16 + g;
            float2 v0 = make_float2(acc[mt][nt][0] + b0, acc[mt][nt][1] + b1);
            float2 v1 = make_float2(acc[mt][nt][2] + b0, acc[mt][nt][3] + b1);
            *(float2*)&C[(size_t)row * N_total + col] = v0;
            *(float2*)&C[(size_t)(row + 8) * N_total + col] = v1;
        }
    }
}

// ---------------- small SIMT GEMM (32-row layer1-bwd projection) ----------------
__global__ void __launch_bounds__(256) gemm_bias(
    const float* __restrict__ A, const float* __restrict__ W,
    const float* __restrict__ bias, float* __restrict__ C,
    int M, int N, int K)
{
    __shared__ float As[16][132];
    __shared__ float Bs[16][132];
    const int bn = blockIdx.x * 128;
    const int bm = blockIdx.y * 128;
    const int tid = threadIdx.x;
    const int tx = tid & 15, ty = tid >> 4;
    const int lrow = tid >> 2;
    const int lk = (tid & 3) << 2;

    float acc[8][8];
#pragma unroll
    for (int i = 0; i < 8; i++)
#pragma unroll
        for (int j = 0; j < 8; j++) acc[i][j] = 0.f;

    for (int k0 = 0; k0 < K; k0 += 16) {
#pragma unroll
        for (int h = 0; h < 2; ++h) {
            int m = bm + lrow + h * 64;
            float4 v = (m < M) ? *(const float4*)&A[(size_t)m * K + k0 + lk]
                               : make_float4(0.f, 0.f, 0.f, 0.f);
            As[lk + 0][lrow + h * 64] = v.x; As[lk + 1][lrow + h * 64] = v.y;
            As[lk + 2][lrow + h * 64] = v.z; As[lk + 3][lrow + h * 64] = v.w;
            int n = bn + lrow + h * 64;
            float4 wv = *(const float4*)&W[(size_t)n * K + lk + k0];
            Bs[lk + 0][lrow + h * 64] = wv.x; Bs[lk + 1][lrow + h * 64] = wv.y;
            Bs[lk + 2][lrow + h * 64] = wv.z; Bs[lk + 3][lrow + h * 64] = wv.w;
        }
        __syncthreads();
#pragma unroll
        for (int k = 0; k < 16; ++k) {
            float a[8], bb[8];
            *(float4*)&a[0]  = *(const float4*)&As[k][ty * 8];
            *(float4*)&a[4]  = *(const float4*)&As[k][ty * 8 + 4];
            *(float4*)&bb[0] = *(const float4*)&Bs[k][tx * 8];
            *(float4*)&bb[4] = *(const float4*)&Bs[k][tx * 8 + 4];
#pragma unroll
            for (int i = 0; i < 8; i++)
#pragma unroll
                for (int j = 0; j < 8; j++) acc[i][j] += a[i] * bb[j];
        }
        __syncthreads();
    }
#pragma unroll
    for (int i = 0; i < 8; i++) {
        int row = bm + ty * 8 + i;
        if (row >= M) continue;
#pragma unroll
        for (int j = 0; j < 8; j += 4) {
            int col = bn + tx * 8 + j;
            float4 o;
            o.x = acc[i][j + 0] + bias[col + 0];
            o.y = acc[i][j + 1] + bias[col + 1];
            o.z = acc[i][j + 2] + bias[col + 2];
            o.w = acc[i][j + 3] + bias[col + 3];
            *(float4*)&C[(size_t)row * N + col] = o;
        }
    }
}

// ---------------- cluster recurrence: st.async v4 scatter (R16) ------------------
// R16 vs R15 (single variable): the scatter is ONE st.async.v4.b32 (16 B) per lane
// instead of 4x b32. Lane = unit(0-3)*8 + peer(0-7); 4 shfls assemble the 4
// batches of one unit. tx messages per dest barrier: 1024 -> 256 per step.
// Barrier structure, RXB=4096, re-arm protocol, mma mapping: R15-verbatim.
template <int LAYER>
__global__ void __cluster_dims__(8, 1, 1) __launch_bounds__(256, 1) rec_kernel(
    const float* __restrict__ xwF, const float* __restrict__ xwB,
    const float* __restrict__ whhF, const float* __restrict__ whhB,
    float* __restrict__ out, bf16* __restrict__ outh, bf16* __restrict__ outl)
{
    constexpr int NB = (LAYER == 0) ? 4 : 2;
    constexpr int XSTR = (LAYER == 0) ? 2048 : 1024;
    constexpr unsigned RXB = 4096;               // bytes per phase per CTA

    __shared__ alignas(16) bf16 hsm[2][256][8];  // [parity][unit][4 batch x (hi,lo)]
    __shared__ alignas(8) unsigned long long mbar[2];

    const int tid  = threadIdx.x;
    const int lane = tid & 31, wid = tid >> 5;
    const unsigned rank = blockIdx.x & 7;
    const unsigned cl   = blockIdx.x >> 3;

    int dir, b0;
    if (LAYER == 0) { dir = cl >> 3; b0 = (cl & 7) * NB; }
    else            { dir = 0;       b0 = cl * NB; }
    const int j0 = rank * 32;

    const float* xw  = dir ? xwB  : xwF;
    const float* whh = dir ? whhB : whhF;

    // ---- W_hh -> register A-fragments; warp w rows: units 4w..4w+3, gates i,f | g,o
    const int g  = lane >> 2, tg = lane & 3;
    const int gr0 = (g >> 2) * 256 + j0 + 4 * wid + (g & 3);   // g<4: gate i; g>=4: gate f
    const int gr1 = gr0 + 512;                                  // gate g / gate o
    uint32_t wh[16][4], wl[16][4];
#pragma unroll
    for (int ks = 0; ks < 16; ++ks) {
        const int k = ks * 16 + tg * 2;
        pack2bf(*(const float2*)&whh[(size_t)gr0 * 256 + k],     wh[ks][0], wl[ks][0]);
        pack2bf(*(const float2*)&whh[(size_t)gr1 * 256 + k],     wh[ks][1], wl[ks][1]);
        pack2bf(*(const float2*)&whh[(size_t)gr0 * 256 + k + 8], wh[ks][2], wl[ks][2]);
        pack2bf(*(const float2*)&whh[(size_t)gr1 * 256 + k + 8], wh[ks][3], wl[ks][3]);
    }

    // zero h buffers (both parities)
    for (int idx = tid; idx < 2 * 256 * 2; idx += 256)
        ((uint32_t*)hsm)[idx * 2] = 0, ((uint32_t*)hsm)[idx * 2 + 1] = 0;
    if (tid == 0) {
        asm volatile("mbarrier.init.shared.b64 [%0], %1;"
                     :: "r"(smem_u32(&mbar[0])), "r"(1u) : "memory");
        asm volatile("mbarrier.init.shared.b64 [%0], %1;"
                     :: "r"(smem_u32(&mbar[1])), "r"(1u) : "memory");
    }
    __syncthreads();
    if (tid == 0) {   // pre-arm: parity1 (t=1) and parity0 (t=2)
        asm volatile("mbarrier.arrive.expect_tx.shared.b64 _, [%0], %1;"
                     :: "r"(smem_u32(&mbar[1])), "r"(RXB) : "memory");
        asm volatile("mbarrier.arrive.expect_tx.shared.b64 _, [%0], %1;"
                     :: "r"(smem_u32(&mbar[0])), "r"(RXB) : "memory");
    }
    __syncthreads();
    // cluster entry barrier: all inits visible before any st.async arrives
    asm volatile("barrier.cluster.arrive.aligned;" ::: "memory");
    asm volatile("barrier.cluster.wait.aligned;" ::: "memory");

    // cell ownership: lanes 0..15 -> (unit 4w + ((lane>>2)&3), batch lane&3)
    const int u_sc  = (lane >> 2) & 3;
    const int bb_   = lane & 3;
    const int unit_g = j0 + 4 * wid + u_sc;
    const bool is_cell = (lane < 16) && (bb_ < NB);

    float c_state = 0.f;
    unsigned ph0 = 0, ph1 = 0;
    const uint32_t mb0 = smem_u32(&mbar[0]), mb1 = smem_u32(&mbar[1]);
    const uint32_t hs_base = smem_u32(&hsm[0][0][0]);
    const uint32_t lrow16 = (uint32_t)(lane & 15) * 16u;

    // xw prefetch (per cell lane), one step ahead
    const size_t xbstep = (size_t)BATCH * XSTR;
    size_t xcell = ((size_t)(dir ? (T_STEPS - 1) : 0) * BATCH + b0 + bb_) * XSTR + unit_g;
    float xn0 = 0.f, xn1 = 0.f, xn2 = 0.f, xn3 = 0.f;
    if (is_cell) {
        xn0 = __ldcs(&xw[xcell]);
        xn1 = __ldcs(&xw[xcell + 256]);
        xn2 = __ldcs(&xw[xcell + 512]);
        xn3 = __ldcs(&xw[xcell + 768]);
    }

    // v4-scatter mapping: lane = unit(0-3)*8 + peer(0-7); stores 16 B row of
    // unit (j0 + 4*wid + u_v4) to peer pr_v4.
    const int u_v4  = lane >> 3;
    const int pr_v4 = lane & 7;
    const int unit_v4 = j0 + 4 * wid + u_v4;
    uint32_t raddr[2], rmb[2];
#pragma unroll
    for (int pp = 0; pp < 2; ++pp) {
        uint32_t laddr = hs_base + (uint32_t)pp * 4096u + (uint32_t)unit_v4 * 16u;
        uint32_t lmb = pp ? mb1 : mb0;
        asm("mapa.shared::cluster.u32 %0, %1, %2;"
            : "=r"(raddr[pp]) : "r"(laddr), "r"(pr_v4));
        asm("mapa.shared::cluster.u32 %0, %1, %2;"
            : "=r"(rmb[pp]) : "r"(lmb), "r"(pr_v4));
    }
    const int sl0 = u_v4 << 2;   // source lanes sl0..sl0+3 hold batches 0..3

    for (int t = 0; t < T_STEPS; ++t) {
        const int tr = dir ? (T_STEPS - 1 - t) : t;
        const int p = t & 1;

        const float xg0 = xn0, xg1 = xn1, xg2 = xn2, xg3 = xn3;
        if (t + 1 < T_STEPS && is_cell) {
            xcell = dir ? (xcell - xbstep) : (xcell + xbstep);
            xn0 = __ldcs(&xw[xcell]);
            xn1 = __ldcs(&xw[xcell + 256]);
            xn2 = __ldcs(&xw[xcell + 512]);
            xn3 = __ldcs(&xw[xcell + 768]);
        }

        if (t > 0) {
            if (p) { mbar_wait_spin(mb1, ph1); ph1 ^= 1; }
            else   { mbar_wait_spin(mb0, ph0); ph0 ^= 1; }
            // re-arm this parity for step t+2 (single thread)
            if (tid == 0)
                asm volatile("mbarrier.arrive.expect_tx.shared.b64 _, [%0], %1;"
                             :: "r"(p ? mb1 : mb0), "r"(RXB) : "memory");
        }

        // ---- HMMA matvec (16 ldsm + 32 mma), two independent chains ----
        const uint32_t hb = hs_base + (uint32_t)p * 4096u + lrow16;
        float dA[4] = {0.f, 0.f, 0.f, 0.f}, eA[4] = {0.f, 0.f, 0.f, 0.f};
        float dB[4] = {0.f, 0.f, 0.f, 0.f}, eB[4] = {0.f, 0.f, 0.f, 0.f};
        {
            uint32_t bbuf[8][2];
#pragma unroll
            for (int ks = 0; ks < 8; ++ks) ldsm2t(bbuf[ks], hb + (uint32_t)ks * 256u);
#pragma unroll
            for (int ks = 0; ks < 8; ++ks) {
                mma_bf16(dA, wh[ks], bbuf[ks]);
                mma_bf16(eA, wl[ks], bbuf[ks]);
            }
#pragma unroll
            for (int ks = 0; ks < 8; ++ks) ldsm2t(bbuf[ks], hb + (uint32_t)(8 + ks) * 256u);
#pragma unroll
            for (int ks = 0; ks < 8; ++ks) {
                mma_bf16(dB, wh[8 + ks], bbuf[ks]);
                mma_bf16(eB, wl[8 + ks], bbuf[ks]);
            }
        }
        const float v0 = (dA[0] + dB[0]) + (dA[1] + dB[1]) + (eA[0] + eB[0]);
        const float v1 = (dA[2] + dB[2]) + (dA[3] + dB[3]) + (eA[2] + eB[2]);

        const float vf = __shfl_down_sync(0xffffffffu, v0, 16);
        const float vo = __shfl_down_sync(0xffffffffu, v1, 16);

        uint32_t pv = 0;
        if (lane < 16) {
            float gi = xg0 + v0;
            float gf = xg1 + vf;
            float gg = xg2 + v1;
            float go = xg3 + vo;
            float ii = sigf(gi), ff = sigf(gf), oo = sigf(go);
            c_state = ff * c_state + ii * tanhf_fast(gg);
            float h = oo * tanhf_fast(c_state);
            bf16 hh, hl; split1(h, hh, hl);
            __nv_bfloat162 pk; pk.x = hh; pk.y = hl;
            pv = *(uint32_t*)&pk;
            if (is_cell) {
                if (LAYER == 0) {
                    size_t oidx = ((size_t)tr * BATCH + (b0 + bb_)) * 512 + (dir << 8) + unit_g;
                    out[oidx] = h;
                    outh[oidx] = hh; outl[oidx] = hl;
                } else if (t == T_STEPS - 1) {
                    out[(b0 + bb_) * 512 + unit_g] = h;
                }
            }
        }
        if (t == T_STEPS - 1) break;

        // assemble the 4 batches of unit u_v4 and send ONE 16 B st.async to peer
        const uint32_t q0 = __shfl_sync(0xffffffffu, pv, sl0 + 0);
        const uint32_t q1 = __shfl_sync(0xffffffffu, pv, sl0 + 1);
        const uint32_t q2 = __shfl_sync(0xffffffffu, pv, sl0 + 2);
        const uint32_t q3 = __shfl_sync(0xffffffffu, pv, sl0 + 3);
        const int pn = p ^ 1;
        asm volatile(
            "st.async.weak.shared::cluster.mbarrier::complete_tx::bytes.v4.b32 "
            "[%0], {%1, %2, %3, %4}, [%5];"
            :: "r"(raddr[pn]), "r"(q0), "r"(q1), "r"(q2), "r"(q3), "r"(rmb[pn])
            : "memory");
    }
}

// ---------------- final: hb1(T-1) one-step + FC -------------------------------
__global__ void final_kernel(const float* __restrict__ fc_w, const float* __restrict__ fc_b,
                             float* __restrict__ outp)
{
    __shared__ float last[512];
    int b = blockIdx.x, tid = threadIdx.x;   // 128 threads
    for (int j = tid; j < 256; j += 128) {
        last[j] = g_LAST[b * 512 + j];
        float gi = g_XWB1L[b * 1024 + j];
        float gg = g_XWB1L[b * 1024 + 512 + j];
        float go = g_XWB1L[b * 1024 + 768 + j];
        float c = sigf(gi) * tanhf_fast(gg);
        last[256 + j] = sigf(go) * tanhf_fast(c);
    }
    __syncthreads();
    float acc = fc_b[tid];
    const float4* w  = (const float4*)&fc_w[(size_t)tid * 512];
    const float4* l4 = (const float4*)last;
#pragma unroll 8
    for (int k = 0; k < 128; ++k) {
        float4 ww = w[k]; float4 ll = l4[k];
        acc += ww.x * ll.x + ww.y * ll.y + ww.z * ll.z + ww.w * ll.w;
    }
    outp[b * 128 + tid] = acc;
}

// ---------------- launch ------------------------------------------------------
extern "C" void kernel_launch(void* const* d_in, const int* in_sizes, int n_in,
                              void* d_out, int out_size)
{
    const float* x     = (const float*)d_in[0];
    const float* wih0f = (const float*)d_in[1];
    const float* whh0f = (const float*)d_in[2];
    const float* b0f   = (const float*)d_in[3];
    const float* wih0b = (const float*)d_in[4];
    const float* whh0b = (const float*)d_in[5];
    const float* b0b   = (const float*)d_in[6];
    const float* wih1f = (const float*)d_in[7];
    const float* whh1f = (const float*)d_in[8];
    const float* b1f   = (const float*)d_in[9];
    const float* wih1b = (const float*)d_in[10];
    const float* whh1b = (const float*)d_in[11];
    const float* b1b   = (const float*)d_in[12];
    const float* fcw   = (const float*)d_in[13];
    const float* fcb   = (const float*)d_in[14];
    float* outp = (float*)d_out;

    float *XW0, *XW1, *OUT0, *LAST, *XWB1L, *B0S;
    bf16 *A0H, *A0L, *O0H, *O0L, *W0SH, *W0SL, *W1FH, *W1FL;
    cudaGetSymbolAddress((void**)&XW0,   g_XW0);
    cudaGetSymbolAddress((void**)&XW1,   g_XW1);
    cudaGetSymbolAddress((void**)&OUT0,  g_OUT0);
    cudaGetSymbolAddress((void**)&LAST,  g_LAST);
    cudaGetSymbolAddress((void**)&XWB1L, g_XWB1L);
    cudaGetSymbolAddress((void**)&B0S,   g_B0S);
    cudaGetSymbolAddress((void**)&A0H,  g_A0H);
    cudaGetSymbolAddress((void**)&A0L,  g_A0L);
    cudaGetSymbolAddress((void**)&O0H,  g_O0H);
    cudaGetSymbolAddress((void**)&O0L,  g_O0L);
    cudaGetSymbolAddress((void**)&W0SH, g_W0SH);
    cudaGetSymbolAddress((void**)&W0SL, g_W0SL);
    cudaGetSymbolAddress((void**)&W1FH, g_W1FH);
    cudaGetSymbolAddress((void**)&W1FL, g_W1FL);

    const int GEMM_SMEM = 82 * 1024;
    cudaFuncSetAttribute(gemm_mma, cudaFuncAttributeMaxDynamicSharedMemorySize, GEMM_SMEM);

    // 1) transpose+split x -> A0 hi/lo
    {
        dim3 tb(32, 8);
        dim3 tg(T_STEPS / 32, INF / 32, BATCH);
        transpose_x<<<tg, tb>>>(x, A0H, A0L);
    }
    // 1b) split weights: layer-0 stacked (+bias concat), layer-1 separate
    split_w0<<<(1024 * 128 + 255) / 256, 256>>>(wih0f, wih0b, W0SH, W0SL,
                                                b0f, b0b, B0S, 1024 * 128);
    split_bf16<<<(1024 * 512 + 255) / 256, 256>>>(wih1f, W1FH, W1FL, 1024 * 512);

    // 2) layer-0 input projections: ONE stacked GEMM, N = 2048 (fwd | bwd)
    {
        dim3 gb(2048 / 128, (T_STEPS * BATCH) / 128);
        gemm_mma<<<gb, 256, GEMM_SMEM>>>(A0H, A0L, W0SH, W0SL, B0S, XW0, INF, 2048);
    }
    // 3) layer-0 bidirectional recurrence -> OUT0
    rec_kernel<0><<<128, 256>>>(XW0, XW0 + 1024, whh0f, whh0b, OUT0, O0H, O0L);
    // 4) layer-1 fwd input projection (K=512, HMMA)
    {
        dim3 gb(1024 / 128, (T_STEPS * BATCH) / 128);
        gemm_mma<<<gb, 256, GEMM_SMEM>>>(O0H, O0L, W1FH, W1FL, b1f, XW1, 512, 1024);
    }
    // 5) layer-1 fwd recurrence -> g_LAST cols 0:256
    rec_kernel<1><<<128, 256>>>(XW1, XW1, whh1f, whh1f, LAST, nullptr, nullptr);
    // 6) layer-1 bwd FIRST step only (t = T-1): one 32-row GEMM (SIMT fp32)
    {
        dim3 gs(1024 / 128, 1);
        gemm_bias<<<gs, 256>>>(OUT0 + (size_t)(T_STEPS - 1) * BATCH * 512,
                               wih1b, b1b, XWB1L, BATCH, 1024, 512);
    }
    // 7) hb1 elementwise + FC
    final_kernel<<<BATCH, 128>>>(fcw, fcb, outp);
}

// round 17
// speedup vs baseline: 1.1170x; 1.1170x over previous
#include <cuda_runtime.h>
#include <cuda_bf16.h>
#include <math.h>
#include <cstdint>

#define T_STEPS 2048
#define BATCH 32
#define INF 128
#define HID 256

typedef unsigned long long ull;
typedef __nv_bfloat16 bf16;

// ---------------- scratch ------------------------------------------------------
__device__ float g_XW0[(size_t)T_STEPS * BATCH * 2048];   // layer-0 stacked fwd|bwd
__device__ float g_XW1[(size_t)T_STEPS * BATCH * 1024];   // layer-1 fwd
__device__ float g_OUT0[(size_t)T_STEPS * BATCH * 512];
__device__ float g_LAST[BATCH * 512];
__device__ float g_XWB1L[BATCH * 1024];
// bf16 hi/lo planes
__device__ bf16 g_A0H[(size_t)T_STEPS * BATCH * INF];
__device__ bf16 g_A0L[(size_t)T_STEPS * BATCH * INF];
__device__ bf16 g_O0H[(size_t)T_STEPS * BATCH * 512];
__device__ bf16 g_O0L[(size_t)T_STEPS * BATCH * 512];
__device__ bf16 g_W0SH[2048 * 128], g_W0SL[2048 * 128];   // stacked layer-0 weights
__device__ bf16 g_W1FH[1024 * 512], g_W1FL[1024 * 512];
__device__ float g_B0S[2048];                              // stacked layer-0 bias

__device__ __forceinline__ float sigf(float x) {
    return __fdividef(1.0f, 1.0f + __expf(-x));
}
__device__ __forceinline__ float tanhf_fast(float x) {
    float e = __expf(2.0f * x);
    return 1.0f - __fdividef(2.0f, e + 1.0f);
}
__device__ __forceinline__ uint32_t smem_u32(const void* p) {
    uint32_t a;
    asm("{ .reg .u64 t; cvta.to.shared.u64 t, %1; cvt.u32.u64 %0, t; }" : "=r"(a) : "l"(p));
    return a;
}
// Tight spin on LOCAL mbarrier (acquire.cluster orders remote st.async data).
__device__ __forceinline__ void mbar_wait_spin(uint32_t addr, unsigned phase) {
    asm volatile(
        "{\n\t.reg .pred P;\n\t"
        "WAIT_%=:\n\t"
        "mbarrier.test_wait.parity.acquire.cluster.shared::cta.b64 P, [%0], %1;\n\t"
        "@!P bra.uni WAIT_%=;\n\t}"
        :: "r"(addr), "r"(phase) : "memory");
}
__device__ __forceinline__ void cp16(uint32_t saddr, const void* gaddr) {
    asm volatile("cp.async.cg.shared.global [%0], [%1], 16;" :: "r"(saddr), "l"(gaddr));
}
__device__ __forceinline__ void ldsm4(uint32_t* r, uint32_t addr) {
    asm volatile("ldmatrix.sync.aligned.m8n8.x4.shared.b16 {%0,%1,%2,%3}, [%4];"
                 : "=r"(r[0]), "=r"(r[1]), "=r"(r[2]), "=r"(r[3]) : "r"(addr));
}
__device__ __forceinline__ void ldsm2t(uint32_t* r, uint32_t addr) {
    asm volatile("ldmatrix.sync.aligned.m8n8.x2.trans.shared.b16 {%0,%1}, [%2];"
                 : "=r"(r[0]), "=r"(r[1]) : "r"(addr));
}
__device__ __forceinline__ void mma_bf16(float* d, const uint32_t* a, const uint32_t* b) {
    asm volatile(
        "mma.sync.aligned.m16n8k16.row.col.f32.bf16.bf16.f32 "
        "{%0,%1,%2,%3}, {%4,%5,%6,%7}, {%8,%9}, {%0,%1,%2,%3};"
        : "+f"(d[0]), "+f"(d[1]), "+f"(d[2]), "+f"(d[3])
        : "r"(a[0]), "r"(a[1]), "r"(a[2]), "r"(a[3]), "r"(b[0]), "r"(b[1]));
}
__device__ __forceinline__ void split1(float v, bf16& h, bf16& l) {
    h = __float2bfloat16(v);
    l = __float2bfloat16(v - __bfloat162float(h));
}
__device__ __forceinline__ void pack2bf(float2 w, uint32_t& hi, uint32_t& lo) {
    bf16 h0, l0, h1, l1;
    split1(w.x, h0, l0); split1(w.y, h1, l1);
    __nv_bfloat162 hv; hv.x = h0; hv.y = h1;
    __nv_bfloat162 lv; lv.x = l0; lv.y = l1;
    hi = *(uint32_t*)&hv; lo = *(uint32_t*)&lv;
}

// ---------------- transpose x[B,1,IN,T] -> A0 hi/lo [(t*B+b), f] -----------------
__global__ void transpose_x(const float* __restrict__ x,
                            bf16* __restrict__ A0h, bf16* __restrict__ A0l) {
    __shared__ float tile[32][33];
    int b = blockIdx.z;
    int f0 = blockIdx.y * 32, t0 = blockIdx.x * 32;
    int tx = threadIdx.x, ty = threadIdx.y;
#pragma unroll
    for (int i = 0; i < 32; i += 8)
        tile[ty + i][tx] = x[((size_t)b * INF + (f0 + ty + i)) * T_STEPS + t0 + tx];
    __syncthreads();
#pragma unroll
    for (int i = 0; i < 32; i += 8) {
        float v = tile[tx][ty + i];
        size_t idx = (((size_t)(t0 + ty + i)) * BATCH + b) * INF + f0 + tx;
        bf16 h, l; split1(v, h, l);
        A0h[idx] = h; A0l[idx] = l;
    }
}

// ---------------- split layer-0 weights into STACKED planes + bias concat --------
__global__ void split_w0(const float* __restrict__ wf, const float* __restrict__ wb,
                         bf16* __restrict__ hiS, bf16* __restrict__ loS,
                         const float* __restrict__ bf_, const float* __restrict__ bb_,
                         float* __restrict__ biasS, int n) {
    int i = blockIdx.x * blockDim.x + threadIdx.x;
    if (i < n) {
        bf16 h, l;
        split1(wf[i], h, l); hiS[i] = h;     loS[i] = l;
        split1(wb[i], h, l); hiS[n + i] = h; loS[n + i] = l;
        if (i < 1024) { biasS[i] = bf_[i]; biasS[1024 + i] = bb_[i]; }
    }
}
__global__ void split_bf16(const float* __restrict__ in, bf16* __restrict__ hi,
                           bf16* __restrict__ lo, int n) {
    int i = blockIdx.x * blockDim.x + threadIdx.x;
    if (i < n) { bf16 h, l; split1(in[i], h, l); hi[i] = h; lo[i] = l; }
}

// ---------------- HMMA split-bf16 GEMM: C = A(f32~hi+lo) * W^T + bias ----------
__global__ void __launch_bounds__(256) gemm_mma(
    const bf16* __restrict__ Ah, const bf16* __restrict__ Al,
    const bf16* __restrict__ Wh, const bf16* __restrict__ Wl,
    const float* __restrict__ bias, float* __restrict__ C,
    int K, int N_total)
{
    extern __shared__ char sraw[];
    const uint32_t base = (smem_u32(sraw) + 127u) & ~127u;
    const uint32_t As = base;
    const uint32_t Bs = base + 40960u;

    const int tid = threadIdx.x;
    const int lane = tid & 31, wid = tid >> 5;
    const int wm = wid & 1, wn = wid >> 1;
    const int bm = blockIdx.y * 128, bn = blockIdx.x * 128;

    const int a_ro = ((lane >> 3) & 1) * 8 + (lane & 7);
    const int a_co = (lane >> 4) * 16;
    const int b_ro = ((lane >> 4) << 3) + (lane & 7);
    const int b_co = ((lane >> 3) & 1) * 16;

    const int c0 = tid * 2;

    float acc[4][4][4];
#pragma unroll
    for (int mt = 0; mt < 4; ++mt)
#pragma unroll
        for (int nt = 0; nt < 4; ++nt)
#pragma unroll
            for (int e = 0; e < 4; ++e) acc[mt][nt][e] = 0.f;

    const int nst = K >> 5;
    int buf = 0;

#pragma unroll
    for (int h = 0; h < 2; ++h) {
        int c = c0 + h, row = c >> 2, blk = c & 3;
        size_t ga = (size_t)(bm + row) * K + blk * 8;
        size_t gw = (size_t)(bn + row) * K + blk * 8;
        uint32_t so = (uint32_t)(row * 80 + blk * 16);
        cp16(As + so,          Ah + ga);
        cp16(As + 10240u + so, Al + ga);
        cp16(Bs + so,          Wh + gw);
        cp16(Bs + 10240u + so, Wl + gw);
    }
    asm volatile("cp.async.commit_group;");

    for (int st = 0; st < nst; ++st) {
        if (st + 1 < nst) {
            const int nb = buf ^ 1;
            const int k0 = (st + 1) * 32;
#pragma unroll
            for (int h = 0; h < 2; ++h) {
                int c = c0 + h, row = c >> 2, blk = c & 3;
                size_t ga = (size_t)(bm + row) * K + k0 + blk * 8;
                size_t gw = (size_t)(bn + row) * K + k0 + blk * 8;
                uint32_t so = (uint32_t)(nb * 20480 + row * 80 + blk * 16);
                cp16(As + so,          Ah + ga);
                cp16(As + 10240u + so, Al + ga);
                cp16(Bs + so,          Wh + gw);
                cp16(Bs + 10240u + so, Wl + gw);
            }
            asm volatile("cp.async.commit_group;");
            asm volatile("cp.async.wait_group 1;");
        } else {
            asm volatile("cp.async.wait_group 0;");
        }
        __syncthreads();

        const uint32_t Ab = As + buf * 20480u;
        const uint32_t Bb = Bs + buf * 20480u;
#pragma unroll
        for (int ks = 0; ks < 2; ++ks) {
            const uint32_t kb = ks * 32u;
            uint32_t bh[2][4], bl[2][4];
#pragma unroll
            for (int pr = 0; pr < 2; ++pr) {
                uint32_t ro = (uint32_t)((wn * 32 + pr * 16 + b_ro) * 80) + kb + b_co;
                ldsm4(bh[pr], Bb + ro);
                ldsm4(bl[pr], Bb + 10240u + ro);
            }
#pragma unroll
            for (int mt = 0; mt < 4; ++mt) {
                uint32_t ah[4], al[4];
                uint32_t ro = (uint32_t)((wm * 64 + mt * 16 + a_ro) * 80) + kb + a_co;
                ldsm4(ah, Ab + ro);
                ldsm4(al, Ab + 10240u + ro);
#pragma unroll
                for (int nt = 0; nt < 4; ++nt) {
                    const uint32_t* bfh = &bh[nt >> 1][(nt & 1) * 2];
                    const uint32_t* bfl = &bl[nt >> 1][(nt & 1) * 2];
                    mma_bf16(acc[mt][nt], ah, bfh);
                    mma_bf16(acc[mt][nt], al, bfh);
                    mma_bf16(acc[mt][nt], ah, bfl);
                }
            }
        }
        __syncthreads();
        buf ^= 1;
    }

    const int g = lane >> 2, tg = lane & 3;
#pragma unroll
    for (int nt = 0; nt < 4; ++nt) {
        const int col = bn + wn * 32 + nt * 8 + tg * 2;
        const float b0 = bias[col], b1 = bias[col + 1];
#pragma unroll
        for (int mt = 0; mt < 4; ++mt) {
            const int row = bm + wm * 64 + mt * 16 + g;
            float2 v0 = make_float2(acc[mt][nt][0] + b0, acc[mt][nt][1] + b1);
            float2 v1 = make_float2(acc[mt][nt][2] + b0, acc[mt][nt][3] + b1);
            *(float2*)&C[(size_t)row * N_total + col] = v0;
            *(float2*)&C[(size_t)(row + 8) * N_total + col] = v1;
        }
    }
}

// ---------------- small SIMT GEMM (32-row layer1-bwd projection) ----------------
__global__ void __launch_bounds__(256) gemm_bias(
    const float* __restrict__ A, const float* __restrict__ W,
    const float* __restrict__ bias, float* __restrict__ C,
    int M, int N, int K)
{
    __shared__ float As[16][132];
    __shared__ float Bs[16][132];
    const int bn = blockIdx.x * 128;
    const int bm = blockIdx.y * 128;
    const int tid = threadIdx.x;
    const int tx = tid & 15, ty = tid >> 4;
    const int lrow = tid >> 2;
    const int lk = (tid & 3) << 2;

    float acc[8][8];
#pragma unroll
    for (int i = 0; i < 8; i++)
#pragma unroll
        for (int j = 0; j < 8; j++) acc[i][j] = 0.f;

    for (int k0 = 0; k0 < K; k0 += 16) {
#pragma unroll
        for (int h = 0; h < 2; ++h) {
            int m = bm + lrow + h * 64;
            float4 v = (m < M) ? *(const float4*)&A[(size_t)m * K + k0 + lk]
                               : make_float4(0.f, 0.f, 0.f, 0.f);
            As[lk + 0][lrow + h * 64] = v.x; As[lk + 1][lrow + h * 64] = v.y;
            As[lk + 2][lrow + h * 64] = v.z; As[lk + 3][lrow + h * 64] = v.w;
            int n = bn + lrow + h * 64;
            float4 wv = *(const float4*)&W[(size_t)n * K + lk + k0];
            Bs[lk + 0][lrow + h * 64] = wv.x; Bs[lk + 1][lrow + h * 64] = wv.y;
            Bs[lk + 2][lrow + h * 64] = wv.z; Bs[lk + 3][lrow + h * 64] = wv.w;
        }
        __syncthreads();
#pragma unroll
        for (int k = 0; k < 16; ++k) {
            float a[8], bb[8];
            *(float4*)&a[0]  = *(const float4*)&As[k][ty * 8];
            *(float4*)&a[4]  = *(const float4*)&As[k][ty * 8 + 4];
            *(float4*)&bb[0] = *(const float4*)&Bs[k][tx * 8];
            *(float4*)&bb[4] = *(const float4*)&Bs[k][tx * 8 + 4];
#pragma unroll
            for (int i = 0; i < 8; i++)
#pragma unroll
                for (int j = 0; j < 8; j++) acc[i][j] += a[i] * bb[j];
        }
        __syncthreads();
    }
#pragma unroll
    for (int i = 0; i < 8; i++) {
        int row = bm + ty * 8 + i;
        if (row >= M) continue;
#pragma unroll
        for (int j = 0; j < 8; j += 4) {
            int col = bn + tx * 8 + j;
            float4 o;
            o.x = acc[i][j + 0] + bias[col + 0];
            o.y = acc[i][j + 1] + bias[col + 1];
            o.z = acc[i][j + 2] + bias[col + 2];
            o.w = acc[i][j + 3] + bias[col + 3];
            *(float4*)&C[(size_t)row * N + col] = o;
        }
    }
}

// ---------------- cluster recurrence: R15 protocol + all-lane redundant cell -----
// R17 vs R15: cell update computed REDUNDANTLY on all 32 lanes (4 parallel shfls
// distribute all four gates to both lane halves); pv is then lane-resident, so
// the post-cell shfl is deleted and the 4x b32 st.async sends issue immediately.
// Global out-stores moved AFTER the sends (off the inter-CTA edge).
template <int LAYER>
__global__ void __cluster_dims__(8, 1, 1) __launch_bounds__(256, 1) rec_kernel(
    const float* __restrict__ xwF, const float* __restrict__ xwB,
    const float* __restrict__ whhF, const float* __restrict__ whhB,
    float* __restrict__ out, bf16* __restrict__ outh, bf16* __restrict__ outl)
{
    constexpr int NB = (LAYER == 0) ? 4 : 2;
    constexpr int XSTR = (LAYER == 0) ? 2048 : 1024;
    constexpr unsigned RXB = 4096;               // bytes per phase per CTA

    __shared__ alignas(16) bf16 hsm[2][256][8];  // [parity][unit][4 batch x (hi,lo)]
    __shared__ alignas(8) unsigned long long mbar[2];

    const int tid  = threadIdx.x;
    const int lane = tid & 31, wid = tid >> 5;
    const unsigned rank = blockIdx.x & 7;
    const unsigned cl   = blockIdx.x >> 3;

    int dir, b0;
    if (LAYER == 0) { dir = cl >> 3; b0 = (cl & 7) * NB; }
    else            { dir = 0;       b0 = cl * NB; }
    const int j0 = rank * 32;

    const float* xw  = dir ? xwB  : xwF;
    const float* whh = dir ? whhB : whhF;

    // ---- W_hh -> register A-fragments; warp w rows: units 4w..4w+3, gates i,f | g,o
    const int g  = lane >> 2, tg = lane & 3;
    const int gr0 = (g >> 2) * 256 + j0 + 4 * wid + (g & 3);   // g<4: gate i; g>=4: gate f
    const int gr1 = gr0 + 512;                                  // gate g / gate o
    uint32_t wh[16][4], wl[16][4];
#pragma unroll
    for (int ks = 0; ks < 16; ++ks) {
        const int k = ks * 16 + tg * 2;
        pack2bf(*(const float2*)&whh[(size_t)gr0 * 256 + k],     wh[ks][0], wl[ks][0]);
        pack2bf(*(const float2*)&whh[(size_t)gr1 * 256 + k],     wh[ks][1], wl[ks][1]);
        pack2bf(*(const float2*)&whh[(size_t)gr0 * 256 + k + 8], wh[ks][2], wl[ks][2]);
        pack2bf(*(const float2*)&whh[(size_t)gr1 * 256 + k + 8], wh[ks][3], wl[ks][3]);
    }

    // zero h buffers (both parities)
    for (int idx = tid; idx < 2 * 256 * 2; idx += 256)
        ((uint32_t*)hsm)[idx * 2] = 0, ((uint32_t*)hsm)[idx * 2 + 1] = 0;
    if (tid == 0) {
        asm volatile("mbarrier.init.shared.b64 [%0], %1;"
                     :: "r"(smem_u32(&mbar[0])), "r"(1u) : "memory");
        asm volatile("mbarrier.init.shared.b64 [%0], %1;"
                     :: "r"(smem_u32(&mbar[1])), "r"(1u) : "memory");
    }
    __syncthreads();
    if (tid == 0) {   // pre-arm: parity1 (t=1) and parity0 (t=2)
        asm volatile("mbarrier.arrive.expect_tx.shared.b64 _, [%0], %1;"
                     :: "r"(smem_u32(&mbar[1])), "r"(RXB) : "memory");
        asm volatile("mbarrier.arrive.expect_tx.shared.b64 _, [%0], %1;"
                     :: "r"(smem_u32(&mbar[0])), "r"(RXB) : "memory");
    }
    __syncthreads();
    // cluster entry barrier: all inits visible before any st.async arrives
    asm volatile("barrier.cluster.arrive.aligned;" ::: "memory");
    asm volatile("barrier.cluster.wait.aligned;" ::: "memory");

    // cell ownership: every lane mirrors cell (unit 4w + ((lane>>2)&3), batch lane&3)
    const int u_sc  = (lane >> 2) & 3;
    const int bb_   = lane & 3;
    const int unit_g = j0 + 4 * wid + u_sc;
    const bool is_x    = (bb_ < NB);                 // lanes that track a live cell
    const bool is_cell = (lane < 16) && is_x;        // lanes that write outputs

    float c_state = 0.f;
    unsigned ph0 = 0, ph1 = 0;
    const uint32_t mb0 = smem_u32(&mbar[0]), mb1 = smem_u32(&mbar[1]);
    const uint32_t hs_base = smem_u32(&hsm[0][0][0]);
    const uint32_t lrow16 = (uint32_t)(lane & 15) * 16u;

    // xw prefetch (all live-cell lanes, both halves), one step ahead
    const size_t xbstep = (size_t)BATCH * XSTR;
    size_t xcell = ((size_t)(dir ? (T_STEPS - 1) : 0) * BATCH + b0 + bb_) * XSTR + unit_g;
    float xn0 = 0.f, xn1 = 0.f, xn2 = 0.f, xn3 = 0.f;
    if (is_x) {
        xn0 = __ldcs(&xw[xcell]);
        xn1 = __ldcs(&xw[xcell + 256]);
        xn2 = __ldcs(&xw[xcell + 512]);
        xn3 = __ldcs(&xw[xcell + 768]);
    }

    // precompute remote data + remote mbarrier addresses (4 peers per lane-half)
    const int pg = (lane >> 4) * 4;
    uint32_t raddr[2][4], rmb[2][4];
#pragma unroll
    for (int pp = 0; pp < 2; ++pp) {
        uint32_t laddr = hs_base + (uint32_t)pp * 4096u +
                         (uint32_t)unit_g * 16u + (uint32_t)bb_ * 4u;
        uint32_t lmb = pp ? mb1 : mb0;
#pragma unroll
        for (int q = 0; q < 4; ++q) {
            asm("mapa.shared::cluster.u32 %0, %1, %2;"
                : "=r"(raddr[pp][q]) : "r"(laddr), "r"(pg + q));
            asm("mapa.shared::cluster.u32 %0, %1, %2;"
                : "=r"(rmb[pp][q]) : "r"(lmb), "r"(pg + q));
        }
    }

    for (int t = 0; t < T_STEPS; ++t) {
        const int tr = dir ? (T_STEPS - 1 - t) : t;
        const int p = t & 1;

        const float xg0 = xn0, xg1 = xn1, xg2 = xn2, xg3 = xn3;
        if (t + 1 < T_STEPS && is_x) {
            xcell = dir ? (xcell - xbstep) : (xcell + xbstep);
            xn0 = __ldcs(&xw[xcell]);
            xn1 = __ldcs(&xw[xcell + 256]);
            xn2 = __ldcs(&xw[xcell + 512]);
            xn3 = __ldcs(&xw[xcell + 768]);
        }

        if (t > 0) {
            if (p) { mbar_wait_spin(mb1, ph1); ph1 ^= 1; }
            else   { mbar_wait_spin(mb0, ph0); ph0 ^= 1; }
            // re-arm this parity for step t+2 (single thread)
            if (tid == 0)
                asm volatile("mbarrier.arrive.expect_tx.shared.b64 _, [%0], %1;"
                             :: "r"(p ? mb1 : mb0), "r"(RXB) : "memory");
        }

        // ---- HMMA matvec (16 ldsm + 32 mma), two independent chains ----
        const uint32_t hb = hs_base + (uint32_t)p * 4096u + lrow16;
        float dA[4] = {0.f, 0.f, 0.f, 0.f}, eA[4] = {0.f, 0.f, 0.f, 0.f};
        float dB[4] = {0.f, 0.f, 0.f, 0.f}, eB[4] = {0.f, 0.f, 0.f, 0.f};
        {
            uint32_t bbuf[8][2];
#pragma unroll
            for (int ks = 0; ks < 8; ++ks) ldsm2t(bbuf[ks], hb + (uint32_t)ks * 256u);
#pragma unroll
            for (int ks = 0; ks < 8; ++ks) {
                mma_bf16(dA, wh[ks], bbuf[ks]);
                mma_bf16(eA, wl[ks], bbuf[ks]);
            }
#pragma unroll
            for (int ks = 0; ks < 8; ++ks) ldsm2t(bbuf[ks], hb + (uint32_t)(8 + ks) * 256u);
#pragma unroll
            for (int ks = 0; ks < 8; ++ks) {
                mma_bf16(dB, wh[8 + ks], bbuf[ks]);
                mma_bf16(eB, wl[8 + ks], bbuf[ks]);
            }
        }
        const float v0 = (dA[0] + dB[0]) + (dA[1] + dB[1]) + (eA[0] + eB[0]);
        const float v1 = (dA[2] + dB[2]) + (dA[3] + dB[3]) + (eA[2] + eB[2]);

        // distribute all 4 gates to BOTH lane halves (4 independent shfls)
        const float sd0 = __shfl_down_sync(0xffffffffu, v0, 16);
        const float sd1 = __shfl_down_sync(0xffffffffu, v1, 16);
        const float su0 = __shfl_up_sync(0xffffffffu, v0, 16);
        const float su1 = __shfl_up_sync(0xffffffffu, v1, 16);
        const bool lo = (lane < 16);

        // ---- cell update on ALL lanes (upper lanes mirror lower) ----
        float gi = xg0 + (lo ? v0 : su0);
        float gf = xg1 + (lo ? sd0 : v0);
        float gg = xg2 + (lo ? v1 : su1);
        float go = xg3 + (lo ? sd1 : v1);
        float ii = sigf(gi), ff = sigf(gf), oo = sigf(go);
        c_state = ff * c_state + ii * tanhf_fast(gg);
        float h = oo * tanhf_fast(c_state);
        bf16 hh, hl; split1(h, hh, hl);
        __nv_bfloat162 pk; pk.x = hh; pk.y = hl;
        const uint32_t pv = *(uint32_t*)&pk;

        if (t == T_STEPS - 1) {
            if (is_cell) {
                if (LAYER == 0) {
                    size_t oidx = ((size_t)tr * BATCH + (b0 + bb_)) * 512 + (dir << 8) + unit_g;
                    out[oidx] = h; outh[oidx] = hh; outl[oidx] = hl;
                } else {
                    out[(b0 + bb_) * 512 + unit_g] = h;
                }
            }
            break;
        }

        // ---- sends FIRST: 4x b32 st.async to peers (proven-fast R15 scatter) ----
        const int pn = p ^ 1;
#pragma unroll
        for (int q = 0; q < 4; ++q) {
            asm volatile(
                "st.async.weak.shared::cluster.mbarrier::complete_tx::bytes.b32 [%0], %1, [%2];"
                :: "r"(raddr[pn][q]), "r"(pv), "r"(rmb[pn][q]) : "memory");
        }

        // ---- global out-stores after sends (off the inter-CTA edge) ----
        if (LAYER == 0 && is_cell) {
            size_t oidx = ((size_t)tr * BATCH + (b0 + bb_)) * 512 + (dir << 8) + unit_g;
            out[oidx] = h; outh[oidx] = hh; outl[oidx] = hl;
        }
    }
}

// ---------------- final: hb1(T-1) one-step + FC -------------------------------
__global__ void final_kernel(const float* __restrict__ fc_w, const float* __restrict__ fc_b,
                             float* __restrict__ outp)
{
    __shared__ float last[512];
    int b = blockIdx.x, tid = threadIdx.x;   // 128 threads
    for (int j = tid; j < 256; j += 128) {
        last[j] = g_LAST[b * 512 + j];
        float gi = g_XWB1L[b * 1024 + j];
        float gg = g_XWB1L[b * 1024 + 512 + j];
        float go = g_XWB1L[b * 1024 + 768 + j];
        float c = sigf(gi) * tanhf_fast(gg);
        last[256 + j] = sigf(go) * tanhf_fast(c);
    }
    __syncthreads();
    float acc = fc_b[tid];
    const float4* w  = (const float4*)&fc_w[(size_t)tid * 512];
    const float4* l4 = (const float4*)last;
#pragma unroll 8
    for (int k = 0; k < 128; ++k) {
        float4 ww = w[k]; float4 ll = l4[k];
        acc += ww.x * ll.x + ww.y * ll.y + ww.z * ll.z + ww.w * ll.w;
    }
    outp[b * 128 + tid] = acc;
}

// ---------------- launch ------------------------------------------------------
extern "C" void kernel_launch(void* const* d_in, const int* in_sizes, int n_in,
                              void* d_out, int out_size)
{
    const float* x     = (const float*)d_in[0];
    const float* wih0f = (const float*)d_in[1];
    const float* whh0f = (const float*)d_in[2];
    const float* b0f   = (const float*)d_in[3];
    const float* wih0b = (const float*)d_in[4];
    const float* whh0b = (const float*)d_in[5];
    const float* b0b   = (const float*)d_in[6];
    const float* wih1f = (const float*)d_in[7];
    const float* whh1f = (const float*)d_in[8];
    const float* b1f   = (const float*)d_in[9];
    const float* wih1b = (const float*)d_in[10];
    const float* whh1b = (const float*)d_in[11];
    const float* b1b   = (const float*)d_in[12];
    const float* fcw   = (const float*)d_in[13];
    const float* fcb   = (const float*)d_in[14];
    float* outp = (float*)d_out;

    float *XW0, *XW1, *OUT0, *LAST, *XWB1L, *B0S;
    bf16 *A0H, *A0L, *O0H, *O0L, *W0SH, *W0SL, *W1FH, *W1FL;
    cudaGetSymbolAddress((void**)&XW0,   g_XW0);
    cudaGetSymbolAddress((void**)&XW1,   g_XW1);
    cudaGetSymbolAddress((void**)&OUT0,  g_OUT0);
    cudaGetSymbolAddress((void**)&LAST,  g_LAST);
    cudaGetSymbolAddress((void**)&XWB1L, g_XWB1L);
    cudaGetSymbolAddress((void**)&B0S,   g_B0S);
    cudaGetSymbolAddress((void**)&A0H,  g_A0H);
    cudaGetSymbolAddress((void**)&A0L,  g_A0L);
    cudaGetSymbolAddress((void**)&O0H,  g_O0H);
    cudaGetSymbolAddress((void**)&O0L,  g_O0L);
    cudaGetSymbolAddress((void**)&W0SH, g_W0SH);
    cudaGetSymbolAddress((void**)&W0SL, g_W0SL);
    cudaGetSymbolAddress((void**)&W1FH, g_W1FH);
    cudaGetSymbolAddress((void**)&W1FL, g_W1FL);

    const int GEMM_SMEM = 82 * 1024;
    cudaFuncSetAttribute(gemm_mma, cudaFuncAttributeMaxDynamicSharedMemorySize, GEMM_SMEM);

    // 1) transpose+split x -> A0 hi/lo
    {
        dim3 tb(32, 8);
        dim3 tg(T_STEPS / 32, INF / 32, BATCH);
        transpose_x<<<tg, tb>>>(x, A0H, A0L);
    }
    // 1b) split weights: layer-0 stacked (+bias concat), layer-1 separate
    split_w0<<<(1024 * 128 + 255) / 256, 256>>>(wih0f, wih0b, W0SH, W0SL,
                                                b0f, b0b, B0S, 1024 * 128);
    split_bf16<<<(1024 * 512 + 255) / 256, 256>>>(wih1f, W1FH, W1FL, 1024 * 512);

    // 2) layer-0 input projections: ONE stacked GEMM, N = 2048 (fwd | bwd)
    {
        dim3 gb(2048 / 128, (T_STEPS * BATCH) / 128);
        gemm_mma<<<gb, 256, GEMM_SMEM>>>(A0H, A0L, W0SH, W0SL, B0S, XW0, INF, 2048);
    }
    // 3) layer-0 bidirectional recurrence -> OUT0
    rec_kernel<0><<<128, 256>>>(XW0, XW0 + 1024, whh0f, whh0b, OUT0, O0H, O0L);
    // 4) layer-1 fwd input projection (K=512, HMMA)
    {
        dim3 gb(1024 / 128, (T_STEPS * BATCH) / 128);
        gemm_mma<<<gb, 256, GEMM_SMEM>>>(O0H, O0L, W1FH, W1FL, b1f, XW1, 512, 1024);
    }
    // 5) layer-1 fwd recurrence -> g_LAST cols 0:256
    rec_kernel<1><<<128, 256>>>(XW1, XW1, whh1f, whh1f, LAST, nullptr, nullptr);
    // 6) layer-1 bwd FIRST step only (t = T-1): one 32-row GEMM (SIMT fp32)
    {
        dim3 gs(1024 / 128, 1);
        gemm_bias<<<gs, 256>>>(OUT0 + (size_t)(T_STEPS - 1) * BATCH * 512,
                               wih1b, b1b, XWB1L, BATCH, 1024, 512);
    }
    // 7) hb1 elementwise + FC
    final_kernel<<<BATCH, 128>>>(fcw, fcb, outp);
}